// round 9
// baseline (speedup 1.0000x reference)
#include <cuda_runtime.h>
#include <cstdint>

#define N_NODES 50000
#define N_EDGES 800000
#define D 96
#define SCAN_TILE 1024
#define NB ((N_NODES + SCAN_TILE - 1) / SCAN_TILE)   // 49

typedef unsigned long long ull;

// ---------------- device scratch (no allocations allowed) -------------------
__device__ int g_cnt[N_NODES];       // per-dst degree (histogram)
__device__ int g_rowptr[N_NODES];    // block-LOCAL exclusive scan of degrees
__device__ int g_bsum[NB];           // per-scan-block totals
__device__ int g_bsumx[NB];          // exclusive scan of block totals
__device__ int g_rank[N_EDGES];      // within-dst rank of each edge
__device__ int g_csr_src[N_EDGES];   // src node per CSR slot
__device__ float g_z2[(size_t)N_NODES * D];  // x @ Wr^T + bl (overlapped GEMM)

// true rowptr[i] = g_rowptr[i] + g_bsumx[i >> 10]

// ---------------- packed f32x2 helpers --------------------------------------
__device__ __forceinline__ ull dup2(float a) {
    ull r; asm("mov.b64 %0, {%1, %1};" : "=l"(r) : "f"(a)); return r;
}
__device__ __forceinline__ void fma2(ull& d, ull a, ull b) {
    asm("fma.rn.f32x2 %0, %1, %2, %0;" : "+l"(d) : "l"(a), "l"(b));
}
__device__ __forceinline__ void fadd2(ull& d, ull a) {
    asm("add.rn.f32x2 %0, %0, %1;" : "+l"(d) : "l"(a));
}
__device__ __forceinline__ ull fmul2(ull a, ull b) {
    ull r; asm("mul.rn.f32x2 %0, %1, %2;" : "=l"(r) : "l"(a), "l"(b)); return r;
}

// ---------------------------------------------------------------------------
// K1: histogram of dst degrees (2 edges/thread); rank = atomicAdd return
// ---------------------------------------------------------------------------
__global__ void k_hist(const int* __restrict__ ei) {
    int i = blockIdx.x * blockDim.x + threadIdx.x;   // pair index
    int e = i * 2;
    if (e >= N_EDGES) return;
    int2 d2 = *reinterpret_cast<const int2*>(ei + N_EDGES + e);
    g_rank[e]     = atomicAdd(&g_cnt[d2.x], 1);
    g_rank[e + 1] = atomicAdd(&g_cnt[d2.y], 1);
}

// ---------------------------------------------------------------------------
// K2a: per-block (1024-node tile) local exclusive scan + block total
// ---------------------------------------------------------------------------
__global__ __launch_bounds__(256) void k_scan1() {
    __shared__ int wsum[8];
    const int blk = blockIdx.x, t = threadIdx.x;
    const int lane = t & 31, wid = t >> 5;
    int idx = blk * SCAN_TILE + t * 4;
    int v[4];
    #pragma unroll
    for (int i = 0; i < 4; i++)
        v[i] = (idx + i < N_NODES) ? g_cnt[idx + i] : 0;
    int tsum = v[0] + v[1] + v[2] + v[3];

    int incl = tsum;
    #pragma unroll
    for (int off = 1; off < 32; off <<= 1) {
        int s = __shfl_up_sync(0xffffffffu, incl, off);
        if (lane >= off) incl += s;
    }
    if (lane == 31) wsum[wid] = incl;
    __syncthreads();
    if (t == 0) {
        int s = 0;
        #pragma unroll
        for (int i = 0; i < 8; i++) { int x = wsum[i]; wsum[i] = s; s += x; }
        g_bsum[blk] = s;
    }
    __syncthreads();
    int excl = wsum[wid] + (incl - tsum);
    #pragma unroll
    for (int i = 0; i < 4; i++) {
        if (idx + i < N_NODES) g_rowptr[idx + i] = excl;
        excl += v[i];
    }
}

// ---------------------------------------------------------------------------
// K2b: tiny exclusive scan of NB block totals
// ---------------------------------------------------------------------------
__global__ void k_scan2() {
    __shared__ int s[NB];
    int t = threadIdx.x;
    if (t < NB) s[t] = g_bsum[t];
    __syncthreads();
    if (t == 0) {
        int a = 0;
        #pragma unroll
        for (int i = 0; i < NB; i++) { int x = s[i]; s[i] = a; a += x; }
    }
    __syncthreads();
    if (t < NB) g_bsumx[t] = s[t];
}

// ---------------------------------------------------------------------------
// K3: atomic-free scatter: slot = rowptr[dst] + bsumx[dst>>10] + rank[e]
// ---------------------------------------------------------------------------
__global__ void k_scatter(const int* __restrict__ ei) {
    int e = blockIdx.x * blockDim.x + threadIdx.x;
    if (e >= N_EDGES) return;
    int dst = ei[N_EDGES + e];
    int p = g_rowptr[dst] + g_bsumx[dst >> 10] + g_rank[e];
    g_csr_src[p] = ei[e];
}

// ---------------------------------------------------------------------------
// K4: warp-per-node mean aggregation, float4-per-lane (lanes 0..23), packed
//     f32x2 accumulate. Unroll 4 neighbors, dual accumulator banks.
// ---------------------------------------------------------------------------
__global__ void k_agg(const float* __restrict__ x, float* __restrict__ out) {
    int gw = (blockIdx.x * blockDim.x + threadIdx.x) >> 5;
    if (gw >= N_NODES) return;
    int lane = threadIdx.x & 31;
    int beg = g_rowptr[gw] + g_bsumx[gw >> 10];
    int end = (gw + 1 < N_NODES)
            ? (g_rowptr[gw + 1] + g_bsumx[(gw + 1) >> 10]) : N_EDGES;

    const bool act = lane < 24;
    const int col = lane * 4;

    ull a0 = 0, a1 = 0, b0 = 0, b1 = 0;

    int j = beg;
    for (; j + 4 <= end; j += 4) {
        int s0 = __ldg(g_csr_src + j + 0);
        int s1 = __ldg(g_csr_src + j + 1);
        int s2 = __ldg(g_csr_src + j + 2);
        int s3 = __ldg(g_csr_src + j + 3);
        if (act) {
            ulonglong2 v0 = *reinterpret_cast<const ulonglong2*>(x + (size_t)s0 * D + col);
            ulonglong2 v1 = *reinterpret_cast<const ulonglong2*>(x + (size_t)s1 * D + col);
            ulonglong2 v2 = *reinterpret_cast<const ulonglong2*>(x + (size_t)s2 * D + col);
            ulonglong2 v3 = *reinterpret_cast<const ulonglong2*>(x + (size_t)s3 * D + col);
            fadd2(a0, v0.x); fadd2(a1, v0.y);
            fadd2(b0, v1.x); fadd2(b1, v1.y);
            fadd2(a0, v2.x); fadd2(a1, v2.y);
            fadd2(b0, v3.x); fadd2(b1, v3.y);
        }
    }
    for (; j < end; j++) {
        int s = __ldg(g_csr_src + j);
        if (act) {
            ulonglong2 v = *reinterpret_cast<const ulonglong2*>(x + (size_t)s * D + col);
            fadd2(a0, v.x); fadd2(a1, v.y);
        }
    }
    fadd2(a0, b0); fadd2(a1, b1);

    int deg = end - beg;
    float inv = (deg > 0) ? 1.0f / (float)deg : 0.0f;
    ull iv = dup2(inv);
    if (act) {
        ulonglong2 r;
        r.x = fmul2(a0, iv);
        r.y = fmul2(a1, iv);
        *reinterpret_cast<ulonglong2*>(out + (size_t)gw * D + col) = r;
    }
}

// ---------------------------------------------------------------------------
// Shared GEMM tiling: BM=128 rows, BN=96 cols, K=96, 256 threads,
// TM=8 x TN=6 per thread, packed fma.rn.f32x2.
// ---------------------------------------------------------------------------
constexpr int BM = 128;
constexpr int BN = 96;
constexpr int TM = 8;
constexpr int TN = 6;
constexpr int LTHREADS = 256;
constexpr int WPAD = 98;
constexpr int SMEM_FLOATS = BM * D + D * WPAD + BN;
constexpr size_t SMEM_BYTES = (size_t)SMEM_FLOATS * sizeof(float);  // ~87 KB

// GEMM core: acc += As_tile @ Ws_tile  (acc as f32x2 pairs)
__device__ __forceinline__ void gemm_core(const float* As, const float* Ws,
                                          int n0, int o0, ull acc[TM][3]) {
    for (int k = 0; k < D; k += 4) {
        ull w[4][3];
        #pragma unroll
        for (int kk = 0; kk < 4; kk++) {
            const float* wr = Ws + (k + kk) * WPAD + o0;
            w[kk][0] = *reinterpret_cast<const ull*>(wr);
            w[kk][1] = *reinterpret_cast<const ull*>(wr + 2);
            w[kk][2] = *reinterpret_cast<const ull*>(wr + 4);
        }
        #pragma unroll
        for (int i = 0; i < TM; i++) {
            float4 av = *reinterpret_cast<const float4*>(As + (n0 + i) * D + k);
            ull ax = dup2(av.x), ay = dup2(av.y), az = dup2(av.z), aw = dup2(av.w);
            fma2(acc[i][0], ax, w[0][0]); fma2(acc[i][1], ax, w[0][1]); fma2(acc[i][2], ax, w[0][2]);
            fma2(acc[i][0], ay, w[1][0]); fma2(acc[i][1], ay, w[1][1]); fma2(acc[i][2], ay, w[1][2]);
            fma2(acc[i][0], az, w[2][0]); fma2(acc[i][1], az, w[2][1]); fma2(acc[i][2], az, w[2][2]);
            fma2(acc[i][0], aw, w[3][0]); fma2(acc[i][1], aw, w[3][1]); fma2(acc[i][2], aw, w[3][2]);
        }
    }
}

__device__ __forceinline__ void stage_tiles(const float* __restrict__ src,
                                            const float* __restrict__ W,
                                            float* As, float* Ws,
                                            int rowBase, int t) {
    for (int idx = t; idx < D * D; idx += LTHREADS) {
        int o = idx / D, k = idx - o * D;
        Ws[k * WPAD + o] = W[o * D + k];
    }
    for (int idx = t; idx < BM * (D / 4); idx += LTHREADS) {
        int r = idx / (D / 4), q = idx - r * (D / 4);
        int node = rowBase + r;
        float4 v = make_float4(0.f, 0.f, 0.f, 0.f);
        if (node < N_NODES)
            v = *reinterpret_cast<const float4*>(src + (size_t)node * D + q * 4);
        *reinterpret_cast<float4*>(As + r * D + q * 4) = v;
    }
}

// ---------------------------------------------------------------------------
// K5a (stream 2, overlapped with CSR build): g_z2 = x @ Wr^T + bl
// ---------------------------------------------------------------------------
__global__ __launch_bounds__(LTHREADS, 2)
void k_z2(const float* __restrict__ x,
          const float* __restrict__ Wr,
          const float* __restrict__ bl)
{
    extern __shared__ float smem[];
    float* As  = smem;
    float* Ws  = smem + BM * D;
    float* bls = Ws + D * WPAD;

    const int t = threadIdx.x;
    const int rowBase = blockIdx.x * BM;
    if (t < BN) bls[t] = bl[t];

    stage_tiles(x, Wr, As, Ws, rowBase, t);
    __syncthreads();

    const int cg = t & 15, rg = t >> 4;
    const int o0 = cg * TN, n0 = rg * TM;

    ull acc[TM][3];
    {
        ull b0 = *reinterpret_cast<const ull*>(bls + o0);
        ull b1 = *reinterpret_cast<const ull*>(bls + o0 + 2);
        ull b2 = *reinterpret_cast<const ull*>(bls + o0 + 4);
        #pragma unroll
        for (int i = 0; i < TM; i++) { acc[i][0] = b0; acc[i][1] = b1; acc[i][2] = b2; }
    }
    gemm_core(As, Ws, n0, o0, acc);

    #pragma unroll
    for (int i = 0; i < TM; i++) {
        int node = rowBase + n0 + i;
        if (node >= N_NODES) continue;
        float* dst = g_z2 + (size_t)node * D + o0;
        #pragma unroll
        for (int j = 0; j < 3; j++)
            *reinterpret_cast<ull*>(dst + 2 * j) = acc[i][j];
    }
}

// ---------------------------------------------------------------------------
// K5b: out = relu(agg_mean @ Wl^T + g_z2)   (agg_mean lives in `out`)
// ---------------------------------------------------------------------------
__global__ __launch_bounds__(LTHREADS, 2)
void k_final(const float* __restrict__ Wl, float* __restrict__ out)
{
    extern __shared__ float smem[];
    float* As = smem;
    float* Ws = smem + BM * D;

    const int t = threadIdx.x;
    const int rowBase = blockIdx.x * BM;

    stage_tiles(out, Wl, As, Ws, rowBase, t);
    __syncthreads();

    const int cg = t & 15, rg = t >> 4;
    const int o0 = cg * TN, n0 = rg * TM;

    ull acc[TM][3];
    #pragma unroll
    for (int i = 0; i < TM; i++) { acc[i][0] = 0; acc[i][1] = 0; acc[i][2] = 0; }
    gemm_core(As, Ws, n0, o0, acc);

    #pragma unroll
    for (int i = 0; i < TM; i++) {
        int node = rowBase + n0 + i;
        if (node >= N_NODES) continue;
        const float* z2 = g_z2 + (size_t)node * D + o0;
        float* dst = out + (size_t)node * D + o0;
        #pragma unroll
        for (int j = 0; j < 3; j++) {
            float lo, hi;
            asm("mov.b64 {%0, %1}, %2;" : "=f"(lo), "=f"(hi) : "l"(acc[i][j]));
            float2 z = *reinterpret_cast<const float2*>(z2 + 2 * j);
            float2 r = make_float2(fmaxf(lo + z.x, 0.f), fmaxf(hi + z.y, 0.f));
            *reinterpret_cast<float2*>(dst + 2 * j) = r;
        }
    }
}

// ---------------------------------------------------------------------------
extern "C" void kernel_launch(void* const* d_in, const int* in_sizes, int n_in,
                              void* d_out, int out_size) {
    const float* x  = (const float*)d_in[0];   // [N, 96]
    const int* ei   = (const int*)d_in[1];     // [2, E]
    const float* Wl = (const float*)d_in[2];   // [96, 96]
    const float* bl = (const float*)d_in[3];   // [96]
    const float* Wr = (const float*)d_in[4];   // [96, 96]
    float* out = (float*)d_out;                // [N, 96]

    static cudaStream_t s2 = nullptr;
    static cudaEvent_t ev_fork = nullptr, ev_join = nullptr;
    static bool attr_done = false;
    if (!attr_done) {
        cudaFuncSetAttribute(k_z2, cudaFuncAttributeMaxDynamicSharedMemorySize,
                             (int)SMEM_BYTES);
        cudaFuncSetAttribute(k_final, cudaFuncAttributeMaxDynamicSharedMemorySize,
                             (int)SMEM_BYTES);
        cudaStreamCreateWithFlags(&s2, cudaStreamNonBlocking);
        cudaEventCreateWithFlags(&ev_fork, cudaEventDisableTiming);
        cudaEventCreateWithFlags(&ev_join, cudaEventDisableTiming);
        attr_done = true;
    }

    const int GEMM_BLOCKS = (N_NODES + BM - 1) / BM;   // 391

    // ---- fork: z2 GEMM on stream 2, overlapped with CSR build ----
    cudaEventRecord(ev_fork, 0);
    cudaStreamWaitEvent(s2, ev_fork, 0);
    k_z2<<<GEMM_BLOCKS, LTHREADS, SMEM_BYTES, s2>>>(x, Wr, bl);
    cudaEventRecord(ev_join, s2);

    // ---- stream 1: CSR build + aggregation ----
    void* cnt_ptr = nullptr;
    cudaGetSymbolAddress(&cnt_ptr, g_cnt);
    cudaMemsetAsync(cnt_ptr, 0, sizeof(int) * N_NODES);

    k_hist<<<(N_EDGES / 2 + 255) / 256, 256>>>(ei);
    k_scan1<<<NB, 256>>>();
    k_scan2<<<1, 64>>>();
    k_scatter<<<(N_EDGES + 255) / 256, 256>>>(ei);
    {
        int warps_per_block = 8;
        int blocks = (N_NODES + warps_per_block - 1) / warps_per_block;
        k_agg<<<blocks, warps_per_block * 32>>>(x, out);
    }

    // ---- join, then final fused GEMM ----
    cudaStreamWaitEvent(0, ev_join, 0);
    k_final<<<GEMM_BLOCKS, LTHREADS, SMEM_BYTES>>>(Wl, out);
}